// round 2
// baseline (speedup 1.0000x reference)
#include <cuda_runtime.h>

// Persistent-kernel STPN, software-pipelined, packed f32x2 math.
// State u = w + f lives in registers. Per step only pre_h = h_{t-1}.(w+f)
// is on the post-barrier critical path; sq/invn/pre_x for step t+1 are
// computed in the shadow of barrier t.

#define NCTA 128
#define NTHR 1024

namespace {
constexpr int kB = 32;
constexpr int kS = 64;
constexpr int kI = 256;
constexpr int kH = 256;
constexpr int kO = 128;
constexpr int kF = 512;
}

typedef unsigned long long u64;

__device__ unsigned g_count;
__device__ unsigned g_phase;
__device__ float g_hbuf[3][kB * kH];

__device__ __forceinline__ unsigned ld_acq(unsigned* p) {
  unsigned v;
  asm volatile("ld.acquire.gpu.u32 %0, [%1];" : "=r"(v) : "l"(p) : "memory");
  return v;
}
__device__ __forceinline__ unsigned atom_add_acqrel(unsigned* p) {
  unsigned o;
  asm volatile("atom.add.acq_rel.gpu.u32 %0, [%1], 1;" : "=r"(o) : "l"(p) : "memory");
  return o;
}
__device__ __forceinline__ void st_rel(unsigned* p, unsigned v) {
  asm volatile("st.release.gpu.u32 [%0], %1;" :: "l"(p), "r"(v) : "memory");
}

// ---- packed f32x2 helpers ----
__device__ __forceinline__ u64 fma2(u64 a, u64 b, u64 c) {
  u64 d; asm("fma.rn.f32x2 %0, %1, %2, %3;" : "=l"(d) : "l"(a), "l"(b), "l"(c));
  return d;
}
__device__ __forceinline__ u64 mul2(u64 a, u64 b) {
  u64 d; asm("mul.rn.f32x2 %0, %1, %2;" : "=l"(d) : "l"(a), "l"(b));
  return d;
}
__device__ __forceinline__ u64 add2(u64 a, u64 b) {
  u64 d; asm("add.rn.f32x2 %0, %1, %2;" : "=l"(d) : "l"(a), "l"(b));
  return d;
}
__device__ __forceinline__ u64 pack2(float lo, float hi) {
  u64 d; asm("mov.b64 %0, {%1, %2};" : "=l"(d) : "f"(lo), "f"(hi));
  return d;
}
__device__ __forceinline__ float2 unpack2(u64 v) {
  float2 r; asm("mov.b64 {%0, %1}, %2;" : "=f"(r.x), "=f"(r.y) : "l"(v));
  return r;
}
__device__ __forceinline__ float tanh_fast(float z) {
  float e = __expf(2.0f * z);
  return 1.0f - __fdividef(2.0f, e + 1.0f);
}

__global__ void __launch_bounds__(NTHR, 1) stpn_kernel(
    const float* __restrict__ x,
    const float* __restrict__ W,
    const float* __restrict__ Lm,
    const float* __restrict__ Gm,
    const float* __restrict__ bias,
    const float* __restrict__ ow,
    const float* __restrict__ ob,
    float* __restrict__ out)
{
  __shared__ u64 sw[2][kF / 2];        // w pairs
  __shared__ u64 slg[2][kF];           // interleaved: [2p]=lambda pair, [2p+1]=gamma pair

  const int tid  = threadIdx.x;
  const int lane = tid & 31;
  const int b    = tid >> 5;           // warp = batch
  const int hr0  = blockIdx.x * 2;     // first h-row
  const int c0   = 4 * lane;

  // stage weights
  {
    const u64* Wp = (const u64*)(W  + hr0 * kF);
    const u64* Lp = (const u64*)(Lm + hr0 * kF);
    const u64* Gp = (const u64*)(Gm + hr0 * kF);
    for (int i = tid; i < kF; i += NTHR) {   // 2 rows x 256 pairs
      int r = i >> 8, p = i & 255;
      sw[r][p]          = Wp[i];
      slg[r][2 * p]     = Lp[i];
      slg[r][2 * p + 1] = Gp[i];
    }
  }
  const float bias0 = bias[hr0];
  const float bias1 = bias[hr0 + 1];

  unsigned phase0 = 0;
  if (tid == 0) phase0 = ld_acq(&g_phase);
  __syncthreads();

  const u64 n1 = pack2(-1.0f, -1.0f);

  // u = w + f; init f=0 -> u = w
  u64 uu[2][8];
#pragma unroll
  for (int r = 0; r < 2; ++r)
#pragma unroll
    for (int k = 0; k < 4; ++k) {
      ulonglong2 wv = *(const ulonglong2*)&sw[r][64 * k + 2 * lane];
      uu[r][2 * k]     = wv.x;
      uu[r][2 * k + 1] = wv.y;
    }

  float invn0, invn1, pxs0, pxs1;

  // sq + pre_x for step tn (pure register math + x loads)
  auto compute_next = [&](int tn) {
    const ulonglong2* xp = (const ulonglong2*)(x + (b * kS + tn) * kI);
    u64 sq0 = 0, sq1 = 0, px0 = 0, px1 = 0;
#pragma unroll
    for (int k = 0; k < 4; ++k) {
      ulonglong2 xv;
      if (k < 2) xv = xp[lane + 32 * k];
      sq0 = fma2(uu[0][2 * k],     uu[0][2 * k],     sq0);
      sq0 = fma2(uu[0][2 * k + 1], uu[0][2 * k + 1], sq0);
      sq1 = fma2(uu[1][2 * k],     uu[1][2 * k],     sq1);
      sq1 = fma2(uu[1][2 * k + 1], uu[1][2 * k + 1], sq1);
      if (k < 2) {
        px0 = fma2(xv.x, uu[0][2 * k],     px0);
        px0 = fma2(xv.y, uu[0][2 * k + 1], px0);
        px1 = fma2(xv.x, uu[1][2 * k],     px1);
        px1 = fma2(xv.y, uu[1][2 * k + 1], px1);
      }
    }
    float2 a0 = unpack2(sq0), a1 = unpack2(sq1);
    float2 b0 = unpack2(px0), b1 = unpack2(px1);
    float s0 = a0.x + a0.y, s1 = a1.x + a1.y;
    float p0 = b0.x + b0.y, p1 = b1.x + b1.y;
#pragma unroll
    for (int off = 16; off; off >>= 1) {
      s0 += __shfl_xor_sync(0xffffffffu, s0, off);
      s1 += __shfl_xor_sync(0xffffffffu, s1, off);
      p0 += __shfl_xor_sync(0xffffffffu, p0, off);
      p1 += __shfl_xor_sync(0xffffffffu, p1, off);
    }
    invn0 = rsqrtf(s0);
    invn1 = rsqrtf(s1);
    pxs0 = p0;
    pxs1 = p1;
  };

  compute_next(0);

  float hn0 = 0.f, hn1 = 0.f;
  int wb = 0, rb = 2;

  for (int t = 0; t < kS; ++t) {
    // ---- wait for h_{t-1} ----
    if (t > 0) {
      if (tid == 0) {
        unsigned tg = phase0 + (unsigned)t;
        while ((int)(ld_acq(&g_phase) - tg) < 0) { }
      }
      __syncthreads();
    }

    // ---- critical path: pre_h -> hn ----
    const ulonglong2* hp = (const ulonglong2*)(&g_hbuf[rb][b * kH]);
    u64 ph0 = 0, ph1 = 0;
    if (t > 0) {
      ulonglong2 hv0 = __ldcg(&hp[lane]);
      ulonglong2 hv1 = __ldcg(&hp[lane + 32]);
      ph0 = fma2(hv0.x, uu[0][4], ph0);
      ph1 = fma2(hv0.x, uu[1][4], ph1);
      ph0 = fma2(hv0.y, uu[0][5], ph0);
      ph1 = fma2(hv0.y, uu[1][5], ph1);
      ph0 = fma2(hv1.x, uu[0][6], ph0);
      ph1 = fma2(hv1.x, uu[1][6], ph1);
      ph0 = fma2(hv1.y, uu[0][7], ph0);
      ph1 = fma2(hv1.y, uu[1][7], ph1);
    }
    float2 q0 = unpack2(ph0), q1 = unpack2(ph1);
    float s0 = q0.x + q0.y, s1 = q1.x + q1.y;
#pragma unroll
    for (int off = 16; off; off >>= 1) {
      s0 += __shfl_xor_sync(0xffffffffu, s0, off);
      s1 += __shfl_xor_sync(0xffffffffu, s1, off);
    }
    hn0 = tanh_fast(fmaf(pxs0 + s0, invn0, bias0));
    hn1 = tanh_fast(fmaf(pxs1 + s1, invn1, bias1));

    if (lane == 0) {
      *(u64*)&g_hbuf[wb][b * kH + hr0] = pack2(hn0, hn1);
    }
    __syncthreads();

    // ---- arrive barrier t ----
    if (tid == 0) {
      unsigned tg = phase0 + (unsigned)(t + 1);
      if (atom_add_acqrel(&g_count) == NCTA - 1) {
        g_count = 0;
        st_rel(&g_phase, tg);
      }
    }

    // ---- u update (overlaps barrier): u' = w + (lam*iv)*(u-w) + (gam*hn)*ti ----
    {
      const u64 iv0 = pack2(invn0, invn0);
      const u64 iv1 = pack2(invn1, invn1);
      const u64 gh0 = pack2(hn0, hn0);
      const u64 gh1 = pack2(hn1, hn1);
      const ulonglong2* xp = (const ulonglong2*)(x + (b * kS + t) * kI);
#pragma unroll
      for (int k = 0; k < 4; ++k) {
        u64 ti0, ti1;
        if (k < 2) {
          ulonglong2 xv = xp[lane + 32 * k];
          ti0 = xv.x; ti1 = xv.y;
        } else if (t == 0) {
          ti0 = 0; ti1 = 0;
        } else {
          ulonglong2 hv = __ldcg(&hp[lane + 32 * (k - 2)]);
          ti0 = hv.x; ti1 = hv.y;
        }
        const int p = 64 * k + 2 * lane;
#pragma unroll
        for (int r = 0; r < 2; ++r) {
          const u64 ivr = r ? iv1 : iv0;
          const u64 ghr = r ? gh1 : gh0;
          ulonglong2 wv  = *(const ulonglong2*)&sw[r][p];
          ulonglong2 lgA = *(const ulonglong2*)&slg[r][2 * p];
          ulonglong2 lgB = *(const ulonglong2*)&slg[r][2 * p + 2];
          // j = 0
          {
            u64 a  = mul2(lgA.x, ivr);           // lam*iv
            u64 fd = fma2(n1, wv.x, uu[r][2*k]); // u - w
            u64 c  = mul2(lgA.y, ghr);           // gam*hn
            u64 e  = fma2(c, ti0, wv.x);         // w + gam*hn*ti
            uu[r][2 * k] = fma2(a, fd, e);
          }
          // j = 1
          {
            u64 a  = mul2(lgB.x, ivr);
            u64 fd = fma2(n1, wv.y, uu[r][2*k+1]);
            u64 c  = mul2(lgB.y, ghr);
            u64 e  = fma2(c, ti1, wv.y);
            uu[r][2 * k + 1] = fma2(a, fd, e);
          }
        }
      }
    }

    // ---- prepare next step (overlaps barrier) ----
    if (t < kS - 1) compute_next(t + 1);

    rb = wb;
    wb = (wb == 2) ? 0 : wb + 1;
  }

  // ---------------- epilogue ----------------
  // f_fin = u - w
  float* fout = out + kB * kO + kB * kH;
#pragma unroll
  for (int r = 0; r < 2; ++r) {
#pragma unroll
    for (int k = 0; k < 4; ++k) {
      ulonglong2 wv = *(const ulonglong2*)&sw[r][64 * k + 2 * lane];
      ulonglong2 fv;
      fv.x = fma2(n1, wv.x, uu[r][2 * k]);
      fv.y = fma2(n1, wv.y, uu[r][2 * k + 1]);
      *(ulonglong2*)&fout[(size_t)(b * kH + hr0 + r) * kF + c0 + 128 * k] = fv;
    }
  }
  if (lane == 0) {
    *(u64*)&out[kB * kO + b * kH + hr0] = pack2(hn0, hn1);
  }

  // tag_space on CTAs 0..31 (needs all CTAs' final h -> wait barrier kS)
  if (blockIdx.x < kB) {
    if (tid == 0) {
      unsigned tg = phase0 + (unsigned)kS;
      while ((int)(ld_acq(&g_phase) - tg) < 0) { }
    }
    __syncthreads();
    const int bb = blockIdx.x;
    const float* hf = &g_hbuf[(kS - 1) % 3][bb * kH];
#pragma unroll
    for (int j = 0; j < 4; ++j) {
      const int oo = (tid >> 5) * 4 + j;
      float p = 0.f;
#pragma unroll
      for (int m = 0; m < 8; ++m) {
        p += __ldcg(&hf[lane + 32 * m]) * ow[oo * kH + lane + 32 * m];
      }
#pragma unroll
      for (int off = 16; off; off >>= 1) p += __shfl_xor_sync(0xffffffffu, p, off);
      if (lane == 0) out[bb * kO + oo] = p + ob[oo];
    }
  }
}

extern "C" void kernel_launch(void* const* d_in, const int* in_sizes, int n_in,
                              void* d_out, int out_size) {
  (void)in_sizes; (void)n_in; (void)out_size;
  stpn_kernel<<<NCTA, NTHR>>>(
      (const float*)d_in[0],
      (const float*)d_in[1],
      (const float*)d_in[2],
      (const float*)d_in[3],
      (const float*)d_in[4],
      (const float*)d_in[5],
      (const float*)d_in[6],
      (float*)d_out);
}

// round 3
// speedup vs baseline: 1.2417x; 1.2417x over previous
#include <cuda_runtime.h>

// Persistent STPN, packed f32x2, per-CTA flag barrier (no contended atomics).
// State u = w + f in registers (16 x u64). Post-barrier critical path is just
// pre = ti.u (16 fma2) + reduce + fast tanh; the u-update and next-step
// norm (sq -> rsqrt) run in the barrier shadow.

#define NCTA 128
#define NTHR 1024

namespace {
constexpr int kB = 32;
constexpr int kS = 64;
constexpr int kI = 256;
constexpr int kH = 256;
constexpr int kO = 128;
constexpr int kF = 512;
}

typedef unsigned long long u64;

__device__ unsigned g_flags[NCTA];     // monotonic: steps completed by CTA j
__device__ float g_hbuf[3][kB * kH];   // triple-buffered hidden state

__device__ __forceinline__ unsigned ld_acq(const unsigned* p) {
  unsigned v;
  asm volatile("ld.acquire.gpu.u32 %0, [%1];" : "=r"(v) : "l"(p) : "memory");
  return v;
}
__device__ __forceinline__ void st_rel(unsigned* p, unsigned v) {
  asm volatile("st.release.gpu.u32 [%0], %1;" :: "l"(p), "r"(v) : "memory");
}
__device__ __forceinline__ u64 fma2(u64 a, u64 b, u64 c) {
  u64 d; asm("fma.rn.f32x2 %0, %1, %2, %3;" : "=l"(d) : "l"(a), "l"(b), "l"(c));
  return d;
}
__device__ __forceinline__ u64 mul2(u64 a, u64 b) {
  u64 d; asm("mul.rn.f32x2 %0, %1, %2;" : "=l"(d) : "l"(a), "l"(b));
  return d;
}
__device__ __forceinline__ u64 pack2(float lo, float hi) {
  u64 d; asm("mov.b64 %0, {%1, %2};" : "=l"(d) : "f"(lo), "f"(hi));
  return d;
}
__device__ __forceinline__ float2 unpack2(u64 v) {
  float2 r; asm("mov.b64 {%0, %1}, %2;" : "=f"(r.x), "=f"(r.y) : "l"(v));
  return r;
}
__device__ __forceinline__ float tanh_fast(float z) {
  float e = __expf(2.0f * z);
  return 1.0f - __fdividef(2.0f, e + 1.0f);
}

__global__ void __launch_bounds__(NTHR, 1) stpn_kernel(
    const float* __restrict__ x,
    const float* __restrict__ W,
    const float* __restrict__ Lm,
    const float* __restrict__ Gm,
    const float* __restrict__ bias,
    const float* __restrict__ ow,
    const float* __restrict__ ob,
    float* __restrict__ out)
{
  __shared__ u64 sw[2][kF / 2];
  __shared__ u64 sl[2][kF / 2];
  __shared__ u64 sg[2][kF / 2];
  __shared__ unsigned s_base;

  const int tid  = threadIdx.x;
  const int lane = tid & 31;
  const int b    = tid >> 5;        // warp = batch
  const int hr0  = blockIdx.x * 2;  // this CTA's two h-rows

  // stage weights as u64 pairs
  {
    const u64* Wp = (const u64*)(W  + hr0 * kF);
    const u64* Lp = (const u64*)(Lm + hr0 * kF);
    const u64* Gp = (const u64*)(Gm + hr0 * kF);
    for (int i = tid; i < kF; i += NTHR) {   // 2 rows x 256 pairs
      const int r = i >> 8, p = i & 255;
      sw[r][p] = Wp[i];
      sl[r][p] = Lp[i];
      sg[r][p] = Gp[i];
    }
  }
  if (tid == 0) s_base = __ldcg(&g_flags[blockIdx.x]);
  const float bias0 = bias[hr0];
  const float bias1 = bias[hr0 + 1];
  __syncthreads();
  const unsigned base = s_base;

  // u-state: uu[r][2k+j] covers cols 128k + 4*lane + 2j (+1). init f=0 -> u=w.
  u64 uu[2][8];
#pragma unroll
  for (int r = 0; r < 2; ++r)
#pragma unroll
    for (int q = 0; q < 8; ++q) uu[r][q] = sw[r][64 * (q >> 1) + 2 * lane + (q & 1)];

  // initial invn from |u|^2
  float invn0, invn1;
  {
    u64 s0p = 0, s1p = 0;
#pragma unroll
    for (int q = 0; q < 8; ++q) {
      s0p = fma2(uu[0][q], uu[0][q], s0p);
      s1p = fma2(uu[1][q], uu[1][q], s1p);
    }
    float2 a0 = unpack2(s0p), a1 = unpack2(s1p);
    float s0 = a0.x + a0.y, s1 = a1.x + a1.y;
#pragma unroll
    for (int off = 16; off; off >>= 1) {
      s0 += __shfl_xor_sync(0xffffffffu, s0, off);
      s1 += __shfl_xor_sync(0xffffffffu, s1, off);
    }
    invn0 = rsqrtf(s0);
    invn1 = rsqrtf(s1);
  }

  float hn0 = 0.f, hn1 = 0.f;
  int wb = 0, rb = 2;

  for (int t = 0; t < kS; ++t) {
    // ---- wait for all CTAs to have published h(t-1) ----
    if (t > 0) {
      if (tid < NCTA) {
        const unsigned tg = base + (unsigned)t;
        while ((int)(ld_acq(&g_flags[tid]) - tg) < 0) { }
      }
      __syncthreads();
    }

    // ---- critical path: pre = ti . u ----
    const u64* xp = (const u64*)(x + (b * kS + t) * kI);
    const u64* hp = (const u64*)(&g_hbuf[rb][b * kH]);
    u64 th0 = 0, th1 = 0, th2 = 0, th3 = 0;
    if (t > 0) {
      th0 = __ldcg(&hp[2 * lane]);
      th1 = __ldcg(&hp[2 * lane + 1]);
      th2 = __ldcg(&hp[64 + 2 * lane]);
      th3 = __ldcg(&hp[64 + 2 * lane + 1]);
    }
    const u64 tx0 = xp[2 * lane];
    const u64 tx1 = xp[2 * lane + 1];
    const u64 tx2 = xp[64 + 2 * lane];
    const u64 tx3 = xp[64 + 2 * lane + 1];

    u64 p0 = mul2(tx0, uu[0][0]);
    u64 p1 = mul2(tx0, uu[1][0]);
    p0 = fma2(tx1, uu[0][1], p0);  p1 = fma2(tx1, uu[1][1], p1);
    p0 = fma2(tx2, uu[0][2], p0);  p1 = fma2(tx2, uu[1][2], p1);
    p0 = fma2(tx3, uu[0][3], p0);  p1 = fma2(tx3, uu[1][3], p1);
    p0 = fma2(th0, uu[0][4], p0);  p1 = fma2(th0, uu[1][4], p1);
    p0 = fma2(th1, uu[0][5], p0);  p1 = fma2(th1, uu[1][5], p1);
    p0 = fma2(th2, uu[0][6], p0);  p1 = fma2(th2, uu[1][6], p1);
    p0 = fma2(th3, uu[0][7], p0);  p1 = fma2(th3, uu[1][7], p1);

    float2 q0 = unpack2(p0), q1 = unpack2(p1);
    float s0 = q0.x + q0.y, s1 = q1.x + q1.y;
#pragma unroll
    for (int off = 16; off; off >>= 1) {
      s0 += __shfl_xor_sync(0xffffffffu, s0, off);
      s1 += __shfl_xor_sync(0xffffffffu, s1, off);
    }
    hn0 = tanh_fast(fmaf(s0, invn0, bias0));
    hn1 = tanh_fast(fmaf(s1, invn1, bias1));

    if (lane == 0) {
      __stcg((u64*)&g_hbuf[wb][b * kH + hr0], pack2(hn0, hn1));
    }
    __syncthreads();
    if (tid == 0) st_rel(&g_flags[blockIdx.x], base + (unsigned)(t + 1));

    // ---- shadow: u' = w + (lam*iv)*(u-w) + (gam*hn)*ti ; accumulate sq ----
    {
      const u64 n1  = pack2(-1.0f, -1.0f);
      const u64 iv0 = pack2(invn0, invn0);
      const u64 iv1 = pack2(invn1, invn1);
      const u64 gh0 = pack2(hn0, hn0);
      const u64 gh1 = pack2(hn1, hn1);
      u64 sq0 = 0, sq1 = 0;
#pragma unroll
      for (int k = 0; k < 4; ++k) {
        u64 ti0, ti1;
        if (k == 0)      { ti0 = tx0; ti1 = tx1; }
        else if (k == 1) { ti0 = tx2; ti1 = tx3; }
        else if (k == 2) { ti0 = th0; ti1 = th1; }
        else             { ti0 = th2; ti1 = th3; }
        const int p = 64 * k + 2 * lane;
#pragma unroll
        for (int r = 0; r < 2; ++r) {
          const u64 ivr = r ? iv1 : iv0;
          const u64 ghr = r ? gh1 : gh0;
          const u64 w0 = sw[r][p],     w1 = sw[r][p + 1];
          const u64 l0 = sl[r][p],     l1 = sl[r][p + 1];
          const u64 g0 = sg[r][p],     g1 = sg[r][p + 1];
          u64& ua = uu[r][2 * k];
          u64& ub = uu[r][2 * k + 1];
          {
            u64 a = mul2(l0, ivr);
            u64 d = fma2(n1, w0, ua);
            u64 e = fma2(mul2(g0, ghr), ti0, w0);
            ua = fma2(a, d, e);
          }
          {
            u64 a = mul2(l1, ivr);
            u64 d = fma2(n1, w1, ub);
            u64 e = fma2(mul2(g1, ghr), ti1, w1);
            ub = fma2(a, d, e);
          }
          if (r == 0) { sq0 = fma2(ua, ua, sq0); sq0 = fma2(ub, ub, sq0); }
          else        { sq1 = fma2(ua, ua, sq1); sq1 = fma2(ub, ub, sq1); }
        }
      }
      if (t < kS - 1) {
        float2 a0 = unpack2(sq0), a1 = unpack2(sq1);
        float s0n = a0.x + a0.y, s1n = a1.x + a1.y;
#pragma unroll
        for (int off = 16; off; off >>= 1) {
          s0n += __shfl_xor_sync(0xffffffffu, s0n, off);
          s1n += __shfl_xor_sync(0xffffffffu, s1n, off);
        }
        invn0 = rsqrtf(s0n);
        invn1 = rsqrtf(s1n);
      }
    }

    rb = wb;
    wb = (wb == 2) ? 0 : wb + 1;
  }

  // ---------------- epilogue ----------------
  // f_fin = u - w
  {
    const u64 n1 = pack2(-1.0f, -1.0f);
    u64* fout = (u64*)(out + kB * kO + kB * kH);
#pragma unroll
    for (int r = 0; r < 2; ++r) {
      u64* rowp = fout + ((size_t)(b * kH + hr0 + r) * kF) / 2;
#pragma unroll
      for (int q = 0; q < 8; ++q) {
        const int p = 64 * (q >> 1) + 2 * lane + (q & 1);
        rowp[p] = fma2(n1, sw[r][p], uu[r][q]);
      }
    }
  }
  if (lane == 0) {
    *(u64*)&out[kB * kO + b * kH + hr0] = pack2(hn0, hn1);
  }

  // tag_space on CTAs 0..31: needs every CTA's final h
  if (blockIdx.x < kB) {
    if (tid < NCTA) {
      const unsigned tg = base + (unsigned)kS;
      while ((int)(ld_acq(&g_flags[tid]) - tg) < 0) { }
    }
    __syncthreads();
    const int bb = blockIdx.x;
    const float* hf = &g_hbuf[(kS - 1) % 3][bb * kH];
#pragma unroll
    for (int j = 0; j < 4; ++j) {
      const int oo = (tid >> 5) * 4 + j;
      float p = 0.f;
#pragma unroll
      for (int m = 0; m < 8; ++m) {
        p += __ldcg(&hf[lane + 32 * m]) * ow[oo * kH + lane + 32 * m];
      }
#pragma unroll
      for (int off = 16; off; off >>= 1) p += __shfl_xor_sync(0xffffffffu, p, off);
      if (lane == 0) out[bb * kO + oo] = p + ob[oo];
    }
  }
}

extern "C" void kernel_launch(void* const* d_in, const int* in_sizes, int n_in,
                              void* d_out, int out_size) {
  (void)in_sizes; (void)n_in; (void)out_size;
  stpn_kernel<<<NCTA, NTHR>>>(
      (const float*)d_in[0],
      (const float*)d_in[1],
      (const float*)d_in[2],
      (const float*)d_in[3],
      (const float*)d_in[4],
      (const float*)d_in[5],
      (const float*)d_in[6],
      (float*)d_out);
}

// round 4
// speedup vs baseline: 1.8981x; 1.5286x over previous
#include <cuda_runtime.h>

// Persistent STPN, packed f32x2, 512 thr/CTA (128 regs/thread -> no spills).
// Warp = (1 h-row, 4 batches); lane covers 16 cols. State u = w + f in
// registers (32 x u64). Per-CTA flag barrier; critical path = pre = ti.u
// (pure register fma2) + warp reduce + fast tanh.

#define NCTA 128
#define NTHR 512

namespace {
constexpr int kB = 32;
constexpr int kS = 64;
constexpr int kI = 256;
constexpr int kH = 256;
constexpr int kO = 128;
constexpr int kF = 512;
}

typedef unsigned long long u64;

__device__ unsigned g_flags[NCTA];
__device__ float g_hbuf[3][kB * kH];

__device__ __forceinline__ unsigned ld_acq(const unsigned* p) {
  unsigned v;
  asm volatile("ld.acquire.gpu.u32 %0, [%1];" : "=r"(v) : "l"(p) : "memory");
  return v;
}
__device__ __forceinline__ void st_rel(unsigned* p, unsigned v) {
  asm volatile("st.release.gpu.u32 [%0], %1;" :: "l"(p), "r"(v) : "memory");
}
__device__ __forceinline__ u64 fma2(u64 a, u64 b, u64 c) {
  u64 d; asm("fma.rn.f32x2 %0, %1, %2, %3;" : "=l"(d) : "l"(a), "l"(b), "l"(c));
  return d;
}
__device__ __forceinline__ u64 mul2(u64 a, u64 b) {
  u64 d; asm("mul.rn.f32x2 %0, %1, %2;" : "=l"(d) : "l"(a), "l"(b));
  return d;
}
__device__ __forceinline__ u64 pack2(float lo, float hi) {
  u64 d; asm("mov.b64 %0, {%1, %2};" : "=l"(d) : "f"(lo), "f"(hi));
  return d;
}
__device__ __forceinline__ float2 unpack2(u64 v) {
  float2 r; asm("mov.b64 {%0, %1}, %2;" : "=f"(r.x), "=f"(r.y) : "l"(v));
  return r;
}
__device__ __forceinline__ float tanh_fast(float z) {
  float e = __expf(2.0f * z);
  return 1.0f - __fdividef(2.0f, e + 1.0f);
}

__global__ void __launch_bounds__(NTHR, 1) stpn_kernel(
    const float* __restrict__ x,
    const float* __restrict__ W,
    const float* __restrict__ Lm,
    const float* __restrict__ Gm,
    const float* __restrict__ bias,
    const float* __restrict__ ow,
    const float* __restrict__ ob,
    float* __restrict__ out)
{
  __shared__ float sw[2][kF];
  __shared__ float sl[2][kF];
  __shared__ float sg[2][kF];
  __shared__ unsigned s_base;

  const int tid  = threadIdx.x;
  const int lane = tid & 31;
  const int wid  = tid >> 5;            // 0..15
  const int row_par = wid & 1;          // which of the CTA's 2 rows
  const int hr0  = blockIdx.x * 2;
  const int row  = hr0 + row_par;
  const int b0   = (wid >> 1) * 4;      // 4 batches per warp

  // stage weights (2 rows x 512 floats per array)
  for (int i = tid; i < 2 * kF; i += NTHR) {
    const int r = i >> 9, c = i & 511;
    sw[r][c] = W[(hr0 + r) * kF + c];
    sl[r][c] = Lm[(hr0 + r) * kF + c];
    sg[r][c] = Gm[(hr0 + r) * kF + c];
  }
  if (tid == 0) s_base = __ldcg(&g_flags[blockIdx.x]);
  const float bias_row = bias[row];
  __syncthreads();
  const unsigned base = s_base;

  const u64* swp = (const u64*)&sw[row_par][0];  // 256 u64
  const u64* slp = (const u64*)&sl[row_par][0];
  const u64* sgp = (const u64*)&sg[row_par][0];

  // u state: uu[b][2k+j] holds cols 128k + 4*lane + 2j (+1). init f=0 -> u=w.
  u64 uu[4][8];
#pragma unroll
  for (int q = 0; q < 8; ++q) {
    const u64 wv = swp[64 * (q >> 1) + 2 * lane + (q & 1)];
#pragma unroll
    for (int b = 0; b < 4; ++b) uu[b][q] = wv;
  }

  // initial invn (identical for all batches: f=0)
  float iv[4];
  {
    u64 sp = mul2(uu[0][0], uu[0][0]);
#pragma unroll
    for (int q = 1; q < 8; ++q) sp = fma2(uu[0][q], uu[0][q], sp);
    float2 a = unpack2(sp);
    float s = a.x + a.y;
#pragma unroll
    for (int off = 16; off; off >>= 1) s += __shfl_xor_sync(0xffffffffu, s, off);
    const float v = rsqrtf(s);
#pragma unroll
    for (int b = 0; b < 4; ++b) iv[b] = v;
  }

  float hn[4] = {0.f, 0.f, 0.f, 0.f};
  int wb = 0, rb = 2;

  const float* xb = x + (size_t)b0 * kS * kI;

  for (int t = 0; t < kS; ++t) {
    // ---- wait for all CTAs' h(t-1) ----
    if (t > 0) {
      if (tid < NCTA) {
        const unsigned tg = base + (unsigned)t;
        while ((int)(ld_acq(&g_flags[tid]) - tg) < 0) { }
      }
      __syncthreads();
    }

    // ---- critical path: pre[b] = ti . u[b] (register-only fma2) ----
    float pre[4];
#pragma unroll
    for (int b = 0; b < 4; ++b) {
      const u64* xp = (const u64*)(xb + ((size_t)b * kS + t) * kI);
      const u64* hp = (const u64*)(&g_hbuf[rb][(b0 + b) * kH]);
      const u64 t0 = xp[2 * lane],      t1 = xp[2 * lane + 1];
      const u64 t2 = xp[64 + 2 * lane], t3 = xp[64 + 2 * lane + 1];
      u64 h0 = 0, h1 = 0, h2 = 0, h3 = 0;
      if (t > 0) {
        h0 = __ldcg(hp + 2 * lane);      h1 = __ldcg(hp + 2 * lane + 1);
        h2 = __ldcg(hp + 64 + 2 * lane); h3 = __ldcg(hp + 64 + 2 * lane + 1);
      }
      u64 acc = mul2(t0, uu[b][0]);
      acc = fma2(t1, uu[b][1], acc);
      acc = fma2(t2, uu[b][2], acc);
      acc = fma2(t3, uu[b][3], acc);
      acc = fma2(h0, uu[b][4], acc);
      acc = fma2(h1, uu[b][5], acc);
      acc = fma2(h2, uu[b][6], acc);
      acc = fma2(h3, uu[b][7], acc);
      float2 a = unpack2(acc);
      pre[b] = a.x + a.y;
    }
#pragma unroll
    for (int off = 16; off; off >>= 1) {
      pre[0] += __shfl_xor_sync(0xffffffffu, pre[0], off);
      pre[1] += __shfl_xor_sync(0xffffffffu, pre[1], off);
      pre[2] += __shfl_xor_sync(0xffffffffu, pre[2], off);
      pre[3] += __shfl_xor_sync(0xffffffffu, pre[3], off);
    }
#pragma unroll
    for (int b = 0; b < 4; ++b)
      hn[b] = tanh_fast(fmaf(pre[b], iv[b], bias_row));

    if (lane == 0) {
      __stcg(&g_hbuf[wb][(b0 + 0) * kH + row], hn[0]);
      __stcg(&g_hbuf[wb][(b0 + 1) * kH + row], hn[1]);
      __stcg(&g_hbuf[wb][(b0 + 2) * kH + row], hn[2]);
      __stcg(&g_hbuf[wb][(b0 + 3) * kH + row], hn[3]);
    }
    __syncthreads();
    if (tid == 0) st_rel(&g_flags[blockIdx.x], base + (unsigned)(t + 1));

    // ---- shadow: u' = w + (lam*iv)*(u-w) + (gam*hn)*ti ; sq accumulate ----
    {
      const u64 n1 = pack2(-1.0f, -1.0f);
      u64 ivp[4], ghp[4], sq[4];
#pragma unroll
      for (int b = 0; b < 4; ++b) {
        ivp[b] = pack2(iv[b], iv[b]);
        ghp[b] = pack2(hn[b], hn[b]);
        sq[b]  = 0;
      }
#pragma unroll
      for (int k = 0; k < 4; ++k) {
        const int p = 64 * k + 2 * lane;
        const u64 w0 = swp[p], w1 = swp[p + 1];
        const u64 l0 = slp[p], l1 = slp[p + 1];
        const u64 g0 = sgp[p], g1 = sgp[p + 1];
#pragma unroll
        for (int b = 0; b < 4; ++b) {
          u64 ti0, ti1;
          if (k < 2) {
            const u64* xp = (const u64*)(xb + ((size_t)b * kS + t) * kI);
            ti0 = xp[64 * k + 2 * lane];
            ti1 = xp[64 * k + 2 * lane + 1];
          } else if (t > 0) {
            const u64* hp = (const u64*)(&g_hbuf[rb][(b0 + b) * kH]);
            ti0 = __ldcg(hp + 64 * (k - 2) + 2 * lane);
            ti1 = __ldcg(hp + 64 * (k - 2) + 2 * lane + 1);
          } else {
            ti0 = 0; ti1 = 0;
          }
          u64& Ua = uu[b][2 * k];
          u64& Ub = uu[b][2 * k + 1];
          {
            const u64 a = mul2(l0, ivp[b]);
            const u64 d = fma2(n1, w0, Ua);
            const u64 e = fma2(mul2(g0, ghp[b]), ti0, w0);
            Ua = fma2(a, d, e);
            sq[b] = fma2(Ua, Ua, sq[b]);
          }
          {
            const u64 a = mul2(l1, ivp[b]);
            const u64 d = fma2(n1, w1, Ub);
            const u64 e = fma2(mul2(g1, ghp[b]), ti1, w1);
            Ub = fma2(a, d, e);
            sq[b] = fma2(Ub, Ub, sq[b]);
          }
        }
      }
      float s[4];
#pragma unroll
      for (int b = 0; b < 4; ++b) {
        float2 a = unpack2(sq[b]);
        s[b] = a.x + a.y;
      }
#pragma unroll
      for (int off = 16; off; off >>= 1) {
        s[0] += __shfl_xor_sync(0xffffffffu, s[0], off);
        s[1] += __shfl_xor_sync(0xffffffffu, s[1], off);
        s[2] += __shfl_xor_sync(0xffffffffu, s[2], off);
        s[3] += __shfl_xor_sync(0xffffffffu, s[3], off);
      }
#pragma unroll
      for (int b = 0; b < 4; ++b) iv[b] = rsqrtf(s[b]);
    }

    rb = wb;
    wb = (wb == 2) ? 0 : wb + 1;
  }

  // ---------------- epilogue ----------------
  {
    const u64 n1 = pack2(-1.0f, -1.0f);
    u64* fout = (u64*)(out + kB * kO + kB * kH);
#pragma unroll
    for (int b = 0; b < 4; ++b) {
      u64* rowp = fout + (size_t)((b0 + b) * kH + row) * (kF / 2);
#pragma unroll
      for (int q = 0; q < 8; ++q) {
        const int p = 64 * (q >> 1) + 2 * lane + (q & 1);
        rowp[p] = fma2(n1, swp[p], uu[b][q]);
      }
    }
  }
  if (lane == 0) {
#pragma unroll
    for (int b = 0; b < 4; ++b)
      out[kB * kO + (b0 + b) * kH + row] = hn[b];
  }

  // tag_space on CTAs 0..31 (needs every CTA's final h)
  if (blockIdx.x < kB) {
    if (tid < NCTA) {
      const unsigned tg = base + (unsigned)kS;
      while ((int)(ld_acq(&g_flags[tid]) - tg) < 0) { }
    }
    __syncthreads();
    const int bb = blockIdx.x;
    const float* hf = &g_hbuf[(kS - 1) % 3][bb * kH];
#pragma unroll
    for (int j = 0; j < 8; ++j) {
      const int oo = wid * 8 + j;
      float p = 0.f;
#pragma unroll
      for (int m = 0; m < 8; ++m) {
        p += __ldcg(&hf[lane + 32 * m]) * ow[oo * kH + lane + 32 * m];
      }
#pragma unroll
      for (int off = 16; off; off >>= 1) p += __shfl_xor_sync(0xffffffffu, p, off);
      if (lane == 0) out[bb * kO + oo] = p + ob[oo];
    }
  }
}

extern "C" void kernel_launch(void* const* d_in, const int* in_sizes, int n_in,
                              void* d_out, int out_size) {
  (void)in_sizes; (void)n_in; (void)out_size;
  stpn_kernel<<<NCTA, NTHR>>>(
      (const float*)d_in[0],
      (const float*)d_in[1],
      (const float*)d_in[2],
      (const float*)d_in[3],
      (const float*)d_in[4],
      (const float*)d_in[5],
      (const float*)d_in[6],
      (float*)d_out);
}